// round 2
// baseline (speedup 1.0000x reference)
#include <cuda_runtime.h>
#include <cstdint>

// ---------------- problem constants ----------------
#define CN 100000      // nodes
#define CE 1600000     // edges
#define CH 128         // hidden
#define CIN 32         // input feat
#define CG 64          // graphs
#define NB_SCAN ((CN + 1023) / 1024)

// ---------------- static device scratch ----------------
__device__ float g_h0[(size_t)CN * CH];
__device__ float g_h1[(size_t)CN * CH];
__device__ float g_mean[(size_t)CN * CH];
__device__ float g_d13[(size_t)CN * 2];
__device__ float g_inv[CN];
__device__ int   g_deg[CN];
__device__ int   g_cur[CN];
__device__ int   g_rowptr[CN];
__device__ int   g_bsums[NB_SCAN + 8];
__device__ int   g_csr[CE];
__device__ float g_gs[CG * 3];
__device__ int   g_gcnt[CG];

// ---------------- kernels ----------------

__global__ void k_zero(int* deg, int* cur, float* gs, int* gcnt, int n) {
    int i = blockIdx.x * blockDim.x + threadIdx.x;
    if (i < n) { deg[i] = 0; cur[i] = 0; }
    if (i < CG * 3) gs[i] = 0.f;
    if (i < CG) gcnt[i] = 0;
}

__global__ void k_hist(const int* __restrict__ ei, int* deg, int E) {
    for (int e = blockIdx.x * blockDim.x + threadIdx.x; e < E; e += gridDim.x * blockDim.x) {
        int d = ei[E + e];   // dst row
        atomicAdd(&deg[d], 1);
    }
}

// exclusive scan of deg -> rowptr (3 stages)
__global__ void k_scan1(const int* __restrict__ deg, int* rowptr, int* bsums, int n) {
    __shared__ int sh[1024];
    int tid = threadIdx.x;
    int i = blockIdx.x * 1024 + tid;
    int v = (i < n) ? deg[i] : 0;
    sh[tid] = v;
    __syncthreads();
    for (int off = 1; off < 1024; off <<= 1) {
        int t = (tid >= off) ? sh[tid - off] : 0;
        __syncthreads();
        sh[tid] += t;
        __syncthreads();
    }
    if (i < n) rowptr[i] = sh[tid] - v;   // exclusive
    if (tid == 1023) bsums[blockIdx.x] = sh[1023];
}

__global__ void k_scan2(int* bsums, int nb) {
    if (threadIdx.x == 0 && blockIdx.x == 0) {
        int acc = 0;
        for (int i = 0; i < nb; i++) { int v = bsums[i]; bsums[i] = acc; acc += v; }
    }
}

__global__ void k_scan3(int* rowptr, const int* __restrict__ bsums,
                        const int* __restrict__ deg, float* inv, int n) {
    int i = blockIdx.x * blockDim.x + threadIdx.x;
    if (i < n) {
        rowptr[i] += bsums[i >> 10];
        int d = deg[i];
        inv[i] = 1.0f / (float)(d > 0 ? d : 1);
    }
}

__global__ void k_fill(const int* __restrict__ ei, const int* __restrict__ rowptr,
                       int* cur, int* csr, int E) {
    for (int e = blockIdx.x * blockDim.x + threadIdx.x; e < E; e += gridDim.x * blockDim.x) {
        int s = ei[e];
        int d = ei[E + e];
        int pos = rowptr[d] + atomicAdd(&cur[d], 1);
        csr[pos] = s;
    }
}

// mean aggregation: one block per node, blockDim = H (feature dim)
__global__ void k_agg(const float* __restrict__ h, const int* __restrict__ rowptr,
                      const int* __restrict__ deg, const float* __restrict__ inv,
                      const int* __restrict__ csr, float* __restrict__ mean, int H) {
    int n = blockIdx.x;
    int t = threadIdx.x;
    int start = rowptr[n];
    int d = deg[n];
    float acc = 0.f;
    for (int i = 0; i < d; i++) {
        int s = __ldg(&csr[start + i]);
        acc += __ldg(&h[(size_t)s * H + t]);
    }
    mean[(size_t)n * H + t] = acc * inv[n];
}

// C[M x 128] = act( A@WA + (B?@WB) + bias ), K in {32,128}, weights K x 128 row-major
__global__ __launch_bounds__(256)
void k_gemm_dual(const float* __restrict__ A, const float* __restrict__ B,
                 const float* __restrict__ WA, const float* __restrict__ WB,
                 const float* __restrict__ bias, float* __restrict__ C,
                 int M, int K, int relu) {
    __shared__ float As[32][132];
    __shared__ float Ws[32][132];
    int tid = threadIdx.x;
    int tx = tid & 15;        // output col group
    int ty = tid >> 4;        // row group
    int m0 = blockIdx.x * 128;

    float acc[8][8];
#pragma unroll
    for (int i = 0; i < 8; i++)
#pragma unroll
        for (int j = 0; j < 8; j++) acc[i][j] = 0.f;

    int nPass = (B != nullptr) ? 2 : 1;
    for (int pass = 0; pass < nPass; ++pass) {
        const float* Ap = pass ? B : A;
        const float* Wp = pass ? WB : WA;
        for (int k0 = 0; k0 < K; k0 += 32) {
            // load A tile (128 rows x 32 k), store k-major
#pragma unroll
            for (int i = 0; i < 16; i++) {
                int lin = tid + 256 * i;     // 0..4095
                int m = lin >> 5, k = lin & 31;
                int gm = m0 + m;
                float v = (gm < M) ? Ap[(size_t)gm * K + k0 + k] : 0.f;
                As[k][m] = v;
            }
            // load W tile (32 k x 128 cols)
#pragma unroll
            for (int i = 0; i < 16; i++) {
                int lin = tid + 256 * i;
                int k = lin >> 7, j = lin & 127;
                Ws[k][j] = Wp[(size_t)(k0 + k) * 128 + j];
            }
            __syncthreads();
#pragma unroll
            for (int k = 0; k < 32; k++) {
                float a[8], w[8];
#pragma unroll
                for (int i = 0; i < 8; i++) a[i] = As[k][ty * 8 + i];
#pragma unroll
                for (int j = 0; j < 8; j++) w[j] = Ws[k][tx * 8 + j];
#pragma unroll
                for (int i = 0; i < 8; i++)
#pragma unroll
                    for (int j = 0; j < 8; j++) acc[i][j] = fmaf(a[i], w[j], acc[i][j]);
            }
            __syncthreads();
        }
    }
    // epilogue
#pragma unroll
    for (int i = 0; i < 8; i++) {
        int gm = m0 + ty * 8 + i;
        if (gm < M) {
#pragma unroll
            for (int j = 0; j < 8; j++) {
                int col = tx * 8 + j;
                float c = acc[i][j] + bias[col];
                if (relu) c = fmaxf(c, 0.f);
                C[(size_t)gm * 128 + col] = c;
            }
        }
    }
}

// per-node: main head dims 0/2, then first aux layer (warp per node)
__global__ void k_final1(const float* __restrict__ h, const float* __restrict__ Wfc,
                         const float* __restrict__ bfc, const float* __restrict__ Wa1,
                         const float* __restrict__ ba1, float* __restrict__ d13,
                         float* __restrict__ a1, int M) {
    int gw = (blockIdx.x * blockDim.x + threadIdx.x) >> 5;
    int lane = threadIdx.x & 31;
    if (gw >= M) return;
    const float* hr = h + (size_t)gw * 128;
    float s0 = 0.f, s2 = 0.f;
    for (int k = lane; k < 128; k += 32) {
        float hv = hr[k];
        s0 += hv * __ldg(&Wfc[k * 3 + 0]);
        s2 += hv * __ldg(&Wfc[k * 3 + 2]);
    }
#pragma unroll
    for (int o = 16; o; o >>= 1) {
        s0 += __shfl_xor_sync(0xffffffffu, s0, o);
        s2 += __shfl_xor_sync(0xffffffffu, s2, o);
    }
    float d1 = s0 + __ldg(&bfc[0]);
    float d3 = s2 + __ldg(&bfc[2]);
    if (lane == 0) { d13[gw * 2] = d1; d13[gw * 2 + 1] = d3; }
    for (int j = lane; j < 128; j += 32) {
        float v = d1 * __ldg(&Wa1[j]) + d3 * __ldg(&Wa1[128 + j]) + __ldg(&ba1[j]);
        a1[(size_t)gw * 128 + j] = fmaxf(v, 0.f);
    }
}

// per-node: aux output + group accumulation (warp per node)
__global__ void k_final3(const float* __restrict__ a2, const float* __restrict__ d13,
                         const float* __restrict__ Wao, const float* __restrict__ bao,
                         const int* __restrict__ batch, float* gs, int* gcnt, int M) {
    int gw = (blockIdx.x * blockDim.x + threadIdx.x) >> 5;
    int lane = threadIdx.x & 31;
    if (gw >= M) return;
    const float* ar = a2 + (size_t)gw * 128;
    float s = 0.f;
    for (int k = lane; k < 128; k += 32) s += ar[k] * __ldg(&Wao[k]);
#pragma unroll
    for (int o = 16; o; o >>= 1) s += __shfl_xor_sync(0xffffffffu, s, o);
    if (lane == 0) {
        float aux = s + __ldg(&bao[0]);
        int b = batch[gw];
        atomicAdd(&gs[b * 3 + 0], d13[gw * 2]);
        atomicAdd(&gs[b * 3 + 1], aux);
        atomicAdd(&gs[b * 3 + 2], d13[gw * 2 + 1]);
        atomicAdd(&gcnt[b], 1);
    }
}

__global__ void k_final4(const float* __restrict__ gs, const int* __restrict__ gcnt,
                         float* __restrict__ out) {
    int i = threadIdx.x;
    if (i < CG * 3) {
        int g = i / 3;
        int c = gcnt[g];
        out[i] = gs[i] / (float)(c > 0 ? c : 1);
    }
}

// ---------------- host launch ----------------
extern "C" void kernel_launch(void* const* d_in, const int* in_sizes, int n_in,
                              void* d_out, int out_size) {
    const float* x     = (const float*)d_in[0];
    const int*   ei    = (const int*)d_in[1];    // int32 (JAX x64 disabled)
    const int*   batch = (const int*)d_in[2];    // int32
    const float* Wl0 = (const float*)d_in[3];
    const float* bl0 = (const float*)d_in[4];
    const float* Wr0 = (const float*)d_in[5];
    const float* Wl1 = (const float*)d_in[6];
    const float* bl1 = (const float*)d_in[7];
    const float* Wr1 = (const float*)d_in[8];
    const float* Wl2 = (const float*)d_in[9];
    const float* bl2 = (const float*)d_in[10];
    const float* Wr2 = (const float*)d_in[11];
    const float* Wfc = (const float*)d_in[12];
    const float* bfc = (const float*)d_in[13];
    const float* Wa1 = (const float*)d_in[14];
    const float* ba1 = (const float*)d_in[15];
    const float* Wa2 = (const float*)d_in[16];
    const float* ba2 = (const float*)d_in[17];
    const float* Wao = (const float*)d_in[18];
    const float* bao = (const float*)d_in[19];
    float* out = (float*)d_out;

    const int N = in_sizes[0] / CIN;
    const int E = in_sizes[1] / 2;

    float *h0, *h1, *mean, *d13, *inv, *gs;
    int *deg, *cur, *rowptr, *bsums, *csr, *gcnt;
    cudaGetSymbolAddress((void**)&h0,     g_h0);
    cudaGetSymbolAddress((void**)&h1,     g_h1);
    cudaGetSymbolAddress((void**)&mean,   g_mean);
    cudaGetSymbolAddress((void**)&d13,    g_d13);
    cudaGetSymbolAddress((void**)&inv,    g_inv);
    cudaGetSymbolAddress((void**)&deg,    g_deg);
    cudaGetSymbolAddress((void**)&cur,    g_cur);
    cudaGetSymbolAddress((void**)&rowptr, g_rowptr);
    cudaGetSymbolAddress((void**)&bsums,  g_bsums);
    cudaGetSymbolAddress((void**)&csr,    g_csr);
    cudaGetSymbolAddress((void**)&gs,     g_gs);
    cudaGetSymbolAddress((void**)&gcnt,   g_gcnt);

    const int nbScan = (N + 1023) / 1024;
    const int gemmBlocks = (N + 127) / 128;
    const int warpNodeBlocks = (N * 32 + 255) / 256;

    // ---- CSR build ----
    k_zero<<<(N + 255) / 256, 256>>>(deg, cur, gs, gcnt, N);
    k_hist<<<4096, 256>>>(ei, deg, E);
    k_scan1<<<nbScan, 1024>>>(deg, rowptr, bsums, N);
    k_scan2<<<1, 32>>>(bsums, nbScan);
    k_scan3<<<(N + 255) / 256, 256>>>(rowptr, bsums, deg, inv, N);
    k_fill<<<4096, 256>>>(ei, rowptr, cur, csr, E);

    // ---- layer 0 (K=32) ----
    k_agg<<<N, CIN>>>(x, rowptr, deg, inv, csr, mean, CIN);
    k_gemm_dual<<<gemmBlocks, 256>>>(mean, x, Wl0, Wr0, bl0, h0, N, CIN, 1);

    // ---- layer 1 (K=128) ----
    k_agg<<<N, CH>>>(h0, rowptr, deg, inv, csr, mean, CH);
    k_gemm_dual<<<gemmBlocks, 256>>>(mean, h0, Wl1, Wr1, bl1, h1, N, CH, 1);

    // ---- layer 2 (K=128) ----
    k_agg<<<N, CH>>>(h1, rowptr, deg, inv, csr, mean, CH);
    k_gemm_dual<<<gemmBlocks, 256>>>(mean, h1, Wl2, Wr2, bl2, h0, N, CH, 1);

    // ---- heads ----
    k_final1<<<warpNodeBlocks, 256>>>(h0, Wfc, bfc, Wa1, ba1, d13, mean, N);
    k_gemm_dual<<<gemmBlocks, 256>>>(mean, nullptr, Wa2, nullptr, ba2, h1, N, CH, 1);
    k_final3<<<warpNodeBlocks, 256>>>(h1, d13, Wao, bao, batch, gs, gcnt, N);
    k_final4<<<1, 256>>>(gs, gcnt, out);
}

// round 3
// speedup vs baseline: 1.2425x; 1.2425x over previous
#include <cuda_runtime.h>
#include <cstdint>

// ---------------- problem constants ----------------
#define CN 100000      // nodes
#define CE 1600000     // edges
#define CH 128         // hidden
#define CIN 32         // input feat
#define CG 64          // graphs
#define NB_SCAN ((CN + 1023) / 1024)

// ---------------- static device scratch ----------------
__device__ float g_h0[(size_t)CN * CH];
__device__ float g_h1[(size_t)CN * CH];
__device__ float g_mean[(size_t)CN * CH];
__device__ float g_d13[(size_t)CN * 2];
__device__ float g_inv[CN];
__device__ int   g_deg[CN];
__device__ int   g_cur[CN];
__device__ int   g_rowptr[CN];
__device__ int   g_bsums[NB_SCAN + 8];
__device__ int   g_csr[CE];
__device__ float g_gs[CG * 3];
__device__ int   g_gcnt[CG];

// ---------------- f32x2 helpers ----------------
__device__ __forceinline__ uint64_t pack2(float x) {
    uint64_t r; asm("mov.b64 %0, {%1, %1};" : "=l"(r) : "f"(x)); return r;
}
__device__ __forceinline__ void ffma2(uint64_t& d, uint64_t a, uint64_t b) {
    asm("fma.rn.f32x2 %0, %1, %2, %0;" : "+l"(d) : "l"(a), "l"(b));
}
__device__ __forceinline__ float2 unpack2(uint64_t v) {
    float2 f; asm("mov.b64 {%0, %1}, %2;" : "=f"(f.x), "=f"(f.y) : "l"(v)); return f;
}

// ---------------- CSR build kernels ----------------

__global__ void k_zero(int* deg, int* cur, float* gs, int* gcnt, int n) {
    int i = blockIdx.x * blockDim.x + threadIdx.x;
    if (i < n) { deg[i] = 0; cur[i] = 0; }
    if (i < CG * 3) gs[i] = 0.f;
    if (i < CG) gcnt[i] = 0;
}

__global__ void k_hist(const int* __restrict__ ei, int* deg, int E) {
    for (int e = blockIdx.x * blockDim.x + threadIdx.x; e < E; e += gridDim.x * blockDim.x) {
        atomicAdd(&deg[ei[E + e]], 1);
    }
}

__global__ void k_scan1(const int* __restrict__ deg, int* rowptr, int* bsums, int n) {
    __shared__ int sh[1024];
    int tid = threadIdx.x;
    int i = blockIdx.x * 1024 + tid;
    int v = (i < n) ? deg[i] : 0;
    sh[tid] = v;
    __syncthreads();
    for (int off = 1; off < 1024; off <<= 1) {
        int t = (tid >= off) ? sh[tid - off] : 0;
        __syncthreads();
        sh[tid] += t;
        __syncthreads();
    }
    if (i < n) rowptr[i] = sh[tid] - v;   // exclusive
    if (tid == 1023) bsums[blockIdx.x] = sh[1023];
}

__global__ void k_scan2(int* bsums, int nb) {
    __shared__ int sh[128];
    int t = threadIdx.x;
    int v = (t < nb) ? bsums[t] : 0;
    sh[t] = v;
    __syncthreads();
    for (int off = 1; off < 128; off <<= 1) {
        int u = (t >= off) ? sh[t - off] : 0;
        __syncthreads();
        sh[t] += u;
        __syncthreads();
    }
    if (t < nb) bsums[t] = sh[t] - v;     // exclusive
}

__global__ void k_scan3(int* rowptr, const int* __restrict__ bsums,
                        const int* __restrict__ deg, float* inv, int n) {
    int i = blockIdx.x * blockDim.x + threadIdx.x;
    if (i < n) {
        rowptr[i] += bsums[i >> 10];
        int d = deg[i];
        inv[i] = 1.0f / (float)(d > 0 ? d : 1);
    }
}

__global__ void k_fill(const int* __restrict__ ei, const int* __restrict__ rowptr,
                       int* cur, int* csr, int E) {
    for (int e = blockIdx.x * blockDim.x + threadIdx.x; e < E; e += gridDim.x * blockDim.x) {
        int s = ei[e];
        int d = ei[E + e];
        int pos = rowptr[d] + atomicAdd(&cur[d], 1);
        csr[pos] = s;
    }
}

// ---------------- aggregation ----------------
// warp per node, H=128, float4 per lane, unroll-4 for MLP
__global__ void k_agg128(const float* __restrict__ h, const int* __restrict__ rowptr,
                         const int* __restrict__ deg, const float* __restrict__ inv,
                         const int* __restrict__ csr, float* __restrict__ mean, int N) {
    int w = (blockIdx.x * blockDim.x + threadIdx.x) >> 5;
    int lane = threadIdx.x & 31;
    if (w >= N) return;
    int start = rowptr[w];
    int d = deg[w];
    float4 acc = make_float4(0.f, 0.f, 0.f, 0.f);
    int i = 0;
    for (; i + 4 <= d; i += 4) {
        int s0 = __ldg(&csr[start + i]);
        int s1 = __ldg(&csr[start + i + 1]);
        int s2 = __ldg(&csr[start + i + 2]);
        int s3 = __ldg(&csr[start + i + 3]);
        float4 v0 = __ldg((const float4*)(h + (size_t)s0 * 128) + lane);
        float4 v1 = __ldg((const float4*)(h + (size_t)s1 * 128) + lane);
        float4 v2 = __ldg((const float4*)(h + (size_t)s2 * 128) + lane);
        float4 v3 = __ldg((const float4*)(h + (size_t)s3 * 128) + lane);
        acc.x += v0.x + v1.x + v2.x + v3.x;
        acc.y += v0.y + v1.y + v2.y + v3.y;
        acc.z += v0.z + v1.z + v2.z + v3.z;
        acc.w += v0.w + v1.w + v2.w + v3.w;
    }
    for (; i < d; i++) {
        int s = __ldg(&csr[start + i]);
        float4 v = __ldg((const float4*)(h + (size_t)s * 128) + lane);
        acc.x += v.x; acc.y += v.y; acc.z += v.z; acc.w += v.w;
    }
    float iv = inv[w];
    acc.x *= iv; acc.y *= iv; acc.z *= iv; acc.w *= iv;
    ((float4*)(mean + (size_t)w * 128))[lane] = acc;
}

// warp per node, H=32, one float per lane, unroll-4
__global__ void k_agg32(const float* __restrict__ h, const int* __restrict__ rowptr,
                        const int* __restrict__ deg, const float* __restrict__ inv,
                        const int* __restrict__ csr, float* __restrict__ mean, int N) {
    int w = (blockIdx.x * blockDim.x + threadIdx.x) >> 5;
    int lane = threadIdx.x & 31;
    if (w >= N) return;
    int start = rowptr[w];
    int d = deg[w];
    float acc = 0.f;
    int i = 0;
    for (; i + 4 <= d; i += 4) {
        int s0 = __ldg(&csr[start + i]);
        int s1 = __ldg(&csr[start + i + 1]);
        int s2 = __ldg(&csr[start + i + 2]);
        int s3 = __ldg(&csr[start + i + 3]);
        acc += __ldg(&h[(size_t)s0 * 32 + lane]) + __ldg(&h[(size_t)s1 * 32 + lane])
             + __ldg(&h[(size_t)s2 * 32 + lane]) + __ldg(&h[(size_t)s3 * 32 + lane]);
    }
    for (; i < d; i++) {
        int s = __ldg(&csr[start + i]);
        acc += __ldg(&h[(size_t)s * 32 + lane]);
    }
    mean[(size_t)w * 32 + lane] = acc * inv[w];
}

// ---------------- FFMA2 dual GEMM ----------------
// C[M x 128] = act( A@WA + (B?@WB) + bias ), weights K x 128 row-major
__global__ __launch_bounds__(256, 2)
void k_gemm_dual(const float* __restrict__ A, const float* __restrict__ B,
                 const float* __restrict__ WA, const float* __restrict__ WB,
                 const float* __restrict__ bias, float* __restrict__ C,
                 int M, int K, int relu) {
    __shared__ __align__(16) float As[32][132];
    __shared__ __align__(16) float Ws[32][132];
    int tid = threadIdx.x;
    int tx = tid & 15;        // output col group (j = tx*8 .. +7)
    int ty = tid >> 4;        // row group (i = ty*8 .. +7)
    int m0 = blockIdx.x * 128;

    uint64_t acc2[8][4];      // [i][j-pair], packed f32x2
#pragma unroll
    for (int i = 0; i < 8; i++)
#pragma unroll
        for (int j = 0; j < 4; j++) acc2[i][j] = 0ull;

    int nPass = (B != nullptr) ? 2 : 1;
    for (int pass = 0; pass < nPass; ++pass) {
        const float* Ap = pass ? B : A;
        const float* Wp = pass ? WB : WA;
        for (int k0 = 0; k0 < K; k0 += 32) {
            // load A tile: 128 rows x 32 k, float4 along k, store k-major
#pragma unroll
            for (int q = 0; q < 4; q++) {
                int lin = tid + 256 * q;          // 0..1023
                int m = lin >> 3;
                int k4 = (lin & 7) << 2;
                int gm = m0 + m;
                float4 v = make_float4(0.f, 0.f, 0.f, 0.f);
                if (gm < M) v = *(const float4*)&Ap[(size_t)gm * K + k0 + k4];
                As[k4 + 0][m] = v.x;
                As[k4 + 1][m] = v.y;
                As[k4 + 2][m] = v.z;
                As[k4 + 3][m] = v.w;
            }
            // load W tile: 32 k x 128 cols, float4 along cols
#pragma unroll
            for (int q = 0; q < 4; q++) {
                int lin = tid + 256 * q;
                int k = lin >> 5;
                int j4 = (lin & 31) << 2;
                *(float4*)&Ws[k][j4] = *(const float4*)&Wp[(size_t)(k0 + k) * 128 + j4];
            }
            __syncthreads();
#pragma unroll
            for (int k = 0; k < 32; k++) {
                ulonglong2 w01 = *(const ulonglong2*)&Ws[k][tx * 8];
                ulonglong2 w23 = *(const ulonglong2*)&Ws[k][tx * 8 + 4];
                uint64_t wp[4] = { w01.x, w01.y, w23.x, w23.y };
                float4 al = *(const float4*)&As[k][ty * 8];
                float4 ah = *(const float4*)&As[k][ty * 8 + 4];
                float av[8] = { al.x, al.y, al.z, al.w, ah.x, ah.y, ah.z, ah.w };
#pragma unroll
                for (int i = 0; i < 8; i++) {
                    uint64_t ap = pack2(av[i]);
                    ffma2(acc2[i][0], ap, wp[0]);
                    ffma2(acc2[i][1], ap, wp[1]);
                    ffma2(acc2[i][2], ap, wp[2]);
                    ffma2(acc2[i][3], ap, wp[3]);
                }
            }
            __syncthreads();
        }
    }
    // epilogue
    float4 b0 = *(const float4*)&bias[tx * 8];
    float4 b1 = *(const float4*)&bias[tx * 8 + 4];
    float bb[8] = { b0.x, b0.y, b0.z, b0.w, b1.x, b1.y, b1.z, b1.w };
#pragma unroll
    for (int i = 0; i < 8; i++) {
        int gm = m0 + ty * 8 + i;
        if (gm < M) {
            float o[8];
#pragma unroll
            for (int jp = 0; jp < 4; jp++) {
                float2 f = unpack2(acc2[i][jp]);
                o[jp * 2] = f.x; o[jp * 2 + 1] = f.y;
            }
#pragma unroll
            for (int j = 0; j < 8; j++) {
                float c = o[j] + bb[j];
                if (relu) c = fmaxf(c, 0.f);
                C[(size_t)gm * 128 + tx * 8 + j] = c;
            }
        }
    }
}

// ---------------- heads ----------------
__global__ void k_final1(const float* __restrict__ h, const float* __restrict__ Wfc,
                         const float* __restrict__ bfc, const float* __restrict__ Wa1,
                         const float* __restrict__ ba1, float* __restrict__ d13,
                         float* __restrict__ a1, int M) {
    int gw = (blockIdx.x * blockDim.x + threadIdx.x) >> 5;
    int lane = threadIdx.x & 31;
    if (gw >= M) return;
    const float* hr = h + (size_t)gw * 128;
    float s0 = 0.f, s2 = 0.f;
    for (int k = lane; k < 128; k += 32) {
        float hv = hr[k];
        s0 += hv * __ldg(&Wfc[k * 3 + 0]);
        s2 += hv * __ldg(&Wfc[k * 3 + 2]);
    }
#pragma unroll
    for (int o = 16; o; o >>= 1) {
        s0 += __shfl_xor_sync(0xffffffffu, s0, o);
        s2 += __shfl_xor_sync(0xffffffffu, s2, o);
    }
    float d1 = s0 + __ldg(&bfc[0]);
    float d3 = s2 + __ldg(&bfc[2]);
    if (lane == 0) { d13[gw * 2] = d1; d13[gw * 2 + 1] = d3; }
    for (int j = lane; j < 128; j += 32) {
        float v = d1 * __ldg(&Wa1[j]) + d3 * __ldg(&Wa1[128 + j]) + __ldg(&ba1[j]);
        a1[(size_t)gw * 128 + j] = fmaxf(v, 0.f);
    }
}

__global__ void k_final3(const float* __restrict__ a2, const float* __restrict__ d13,
                         const float* __restrict__ Wao, const float* __restrict__ bao,
                         const int* __restrict__ batch, float* gs, int* gcnt, int M) {
    int gw = (blockIdx.x * blockDim.x + threadIdx.x) >> 5;
    int lane = threadIdx.x & 31;
    if (gw >= M) return;
    const float* ar = a2 + (size_t)gw * 128;
    float s = 0.f;
    for (int k = lane; k < 128; k += 32) s += ar[k] * __ldg(&Wao[k]);
#pragma unroll
    for (int o = 16; o; o >>= 1) s += __shfl_xor_sync(0xffffffffu, s, o);
    if (lane == 0) {
        float aux = s + __ldg(&bao[0]);
        int b = batch[gw];
        atomicAdd(&gs[b * 3 + 0], d13[gw * 2]);
        atomicAdd(&gs[b * 3 + 1], aux);
        atomicAdd(&gs[b * 3 + 2], d13[gw * 2 + 1]);
        atomicAdd(&gcnt[b], 1);
    }
}

__global__ void k_final4(const float* __restrict__ gs, const int* __restrict__ gcnt,
                         float* __restrict__ out) {
    int i = threadIdx.x;
    if (i < CG * 3) {
        int g = i / 3;
        int c = gcnt[g];
        out[i] = gs[i] / (float)(c > 0 ? c : 1);
    }
}

// ---------------- host launch ----------------
extern "C" void kernel_launch(void* const* d_in, const int* in_sizes, int n_in,
                              void* d_out, int out_size) {
    const float* x     = (const float*)d_in[0];
    const int*   ei    = (const int*)d_in[1];
    const int*   batch = (const int*)d_in[2];
    const float* Wl0 = (const float*)d_in[3];
    const float* bl0 = (const float*)d_in[4];
    const float* Wr0 = (const float*)d_in[5];
    const float* Wl1 = (const float*)d_in[6];
    const float* bl1 = (const float*)d_in[7];
    const float* Wr1 = (const float*)d_in[8];
    const float* Wl2 = (const float*)d_in[9];
    const float* bl2 = (const float*)d_in[10];
    const float* Wr2 = (const float*)d_in[11];
    const float* Wfc = (const float*)d_in[12];
    const float* bfc = (const float*)d_in[13];
    const float* Wa1 = (const float*)d_in[14];
    const float* ba1 = (const float*)d_in[15];
    const float* Wa2 = (const float*)d_in[16];
    const float* ba2 = (const float*)d_in[17];
    const float* Wao = (const float*)d_in[18];
    const float* bao = (const float*)d_in[19];
    float* out = (float*)d_out;

    const int N = in_sizes[0] / CIN;
    const int E = in_sizes[1] / 2;

    float *h0, *h1, *mean, *d13, *inv, *gs;
    int *deg, *cur, *rowptr, *bsums, *csr, *gcnt;
    cudaGetSymbolAddress((void**)&h0,     g_h0);
    cudaGetSymbolAddress((void**)&h1,     g_h1);
    cudaGetSymbolAddress((void**)&mean,   g_mean);
    cudaGetSymbolAddress((void**)&d13,    g_d13);
    cudaGetSymbolAddress((void**)&inv,    g_inv);
    cudaGetSymbolAddress((void**)&deg,    g_deg);
    cudaGetSymbolAddress((void**)&cur,    g_cur);
    cudaGetSymbolAddress((void**)&rowptr, g_rowptr);
    cudaGetSymbolAddress((void**)&bsums,  g_bsums);
    cudaGetSymbolAddress((void**)&csr,    g_csr);
    cudaGetSymbolAddress((void**)&gs,     g_gs);
    cudaGetSymbolAddress((void**)&gcnt,   g_gcnt);

    const int nbScan = (N + 1023) / 1024;
    const int gemmBlocks = (N + 127) / 128;
    const int warpNodeBlocks = (N * 32 + 255) / 256;

    // ---- CSR build ----
    k_zero<<<(N + 255) / 256, 256>>>(deg, cur, gs, gcnt, N);
    k_hist<<<4096, 256>>>(ei, deg, E);
    k_scan1<<<nbScan, 1024>>>(deg, rowptr, bsums, N);
    k_scan2<<<1, 128>>>(bsums, nbScan);
    k_scan3<<<(N + 255) / 256, 256>>>(rowptr, bsums, deg, inv, N);
    k_fill<<<4096, 256>>>(ei, rowptr, cur, csr, E);

    // ---- layer 0 (K=32) ----
    k_agg32<<<warpNodeBlocks, 256>>>(x, rowptr, deg, inv, csr, mean, N);
    k_gemm_dual<<<gemmBlocks, 256>>>(mean, x, Wl0, Wr0, bl0, h0, N, CIN, 1);

    // ---- layer 1 (K=128) ----
    k_agg128<<<warpNodeBlocks, 256>>>(h0, rowptr, deg, inv, csr, mean, N);
    k_gemm_dual<<<gemmBlocks, 256>>>(mean, h0, Wl1, Wr1, bl1, h1, N, CH, 1);

    // ---- layer 2 (K=128) ----
    k_agg128<<<warpNodeBlocks, 256>>>(h1, rowptr, deg, inv, csr, mean, N);
    k_gemm_dual<<<gemmBlocks, 256>>>(mean, h1, Wl2, Wr2, bl2, h0, N, CH, 1);

    // ---- heads ----
    k_final1<<<warpNodeBlocks, 256>>>(h0, Wfc, bfc, Wa1, ba1, d13, mean, N);
    k_gemm_dual<<<gemmBlocks, 256>>>(mean, nullptr, Wa2, nullptr, ba2, h1, N, CH, 1);
    k_final3<<<warpNodeBlocks, 256>>>(h1, d13, Wao, bao, batch, gs, gcnt, N);
    k_final4<<<1, 256>>>(gs, gcnt, out);
}

// round 5
// speedup vs baseline: 1.6589x; 1.3351x over previous
#include <cuda_runtime.h>
#include <cuda_bf16.h>
#include <cstdint>

// ---------------- problem constants ----------------
#define CN 100000      // nodes
#define CE 1600000     // edges
#define CH 128         // hidden
#define CIN 32         // input feat
#define CG 64          // graphs
#define NB_SCAN ((CN + 1023) / 1024)

// ---------------- static device scratch ----------------
__device__ float g_h0[(size_t)CN * CH];
__device__ float g_h1[(size_t)CN * CH];
__device__ float g_mean[(size_t)CN * CH];
__device__ float g_d13[(size_t)CN * 2];
__device__ float g_inv[CN];
__device__ int   g_deg[CN];
__device__ int   g_cur[CN];
__device__ int   g_rowptr[CN];
__device__ int   g_bsums[NB_SCAN + 8];
__device__ int   g_csr[CE];
__device__ float g_gs[CG * 3];
__device__ int   g_gcnt[CG];
// transposed weight buffers: [N=128][Ktot] K-major
__device__ float g_wt0[128 * 64];     // [Wl0;Wr0]^T  Ktot=64
__device__ float g_wt1[128 * 256];    // [Wl1;Wr1]^T  Ktot=256
__device__ float g_wt2[128 * 256];    // [Wl2;Wr2]^T  Ktot=256
__device__ float g_wta[128 * 128];    // Wa2^T        Ktot=128

// ---------------- mma helper ----------------
__device__ __forceinline__ void mma_bf16(float* d, const uint32_t* a, const uint32_t* b) {
    asm volatile(
        "mma.sync.aligned.m16n8k16.row.col.f32.bf16.bf16.f32 "
        "{%0,%1,%2,%3}, {%4,%5,%6,%7}, {%8,%9}, {%0,%1,%2,%3};"
        : "+f"(d[0]), "+f"(d[1]), "+f"(d[2]), "+f"(d[3])
        : "r"(a[0]), "r"(a[1]), "r"(a[2]), "r"(a[3]), "r"(b[0]), "r"(b[1]));
}

// split one float into bf16 hi/lo
__device__ __forceinline__ void bf16_split(float v, __nv_bfloat16& h, __nv_bfloat16& l) {
    h = __float2bfloat16_rn(v);
    l = __float2bfloat16_rn(v - __bfloat162float(h));
}
__device__ __forceinline__ uint32_t pack_bf(__nv_bfloat16 a, __nv_bfloat16 b) {
    __nv_bfloat162 t; t.x = a; t.y = b;
    return *(uint32_t*)&t;
}

// ---------------- CSR build kernels ----------------
__global__ void k_zero(int* deg, int* cur, float* gs, int* gcnt, int n) {
    int i = blockIdx.x * blockDim.x + threadIdx.x;
    if (i < n) { deg[i] = 0; cur[i] = 0; }
    if (i < CG * 3) gs[i] = 0.f;
    if (i < CG) gcnt[i] = 0;
}

__global__ void k_hist(const int* __restrict__ ei, int* deg, int E) {
    for (int e = blockIdx.x * blockDim.x + threadIdx.x; e < E; e += gridDim.x * blockDim.x)
        atomicAdd(&deg[ei[E + e]], 1);
}

__global__ void k_scan1(const int* __restrict__ deg, int* rowptr, int* bsums, int n) {
    __shared__ int sh[1024];
    int tid = threadIdx.x;
    int i = blockIdx.x * 1024 + tid;
    int v = (i < n) ? deg[i] : 0;
    sh[tid] = v;
    __syncthreads();
    for (int off = 1; off < 1024; off <<= 1) {
        int t = (tid >= off) ? sh[tid - off] : 0;
        __syncthreads();
        sh[tid] += t;
        __syncthreads();
    }
    if (i < n) rowptr[i] = sh[tid] - v;
    if (tid == 1023) bsums[blockIdx.x] = sh[1023];
}

__global__ void k_scan2(int* bsums, int nb) {
    __shared__ int sh[128];
    int t = threadIdx.x;
    int v = (t < nb) ? bsums[t] : 0;
    sh[t] = v;
    __syncthreads();
    for (int off = 1; off < 128; off <<= 1) {
        int u = (t >= off) ? sh[t - off] : 0;
        __syncthreads();
        sh[t] += u;
        __syncthreads();
    }
    if (t < nb) bsums[t] = sh[t] - v;
}

__global__ void k_scan3(int* rowptr, const int* __restrict__ bsums,
                        const int* __restrict__ deg, float* inv, int n) {
    int i = blockIdx.x * blockDim.x + threadIdx.x;
    if (i < n) {
        rowptr[i] += bsums[i >> 10];
        int d = deg[i];
        inv[i] = 1.0f / (float)(d > 0 ? d : 1);
    }
}

__global__ void k_fill(const int* __restrict__ ei, const int* __restrict__ rowptr,
                       int* cur, int* csr, int E) {
    for (int e = blockIdx.x * blockDim.x + threadIdx.x; e < E; e += gridDim.x * blockDim.x) {
        int s = ei[e];
        int d = ei[E + e];
        int pos = rowptr[d] + atomicAdd(&cur[d], 1);
        csr[pos] = s;
    }
}

// ---------------- weight transpose prep ----------------
__global__ void k_prep(const float* Wl0, const float* Wr0, const float* Wl1, const float* Wr1,
                       const float* Wl2, const float* Wr2, const float* Wa2,
                       float* wt0, float* wt1, float* wt2, float* wta) {
    int i = blockIdx.x * blockDim.x + threadIdx.x;
    if (i < 8192) {                      // wt0: [128][64]
        int n = i >> 6, k = i & 63;
        wt0[i] = (k < 32) ? Wl0[k * 128 + n] : Wr0[(k - 32) * 128 + n];
    }
    int j = i - 8192;
    if (j >= 0 && j < 32768) {           // wt1: [128][256]
        int n = j >> 8, k = j & 255;
        wt1[j] = (k < 128) ? Wl1[k * 128 + n] : Wr1[(k - 128) * 128 + n];
    }
    int l = i - 40960;
    if (l >= 0 && l < 32768) {           // wt2
        int n = l >> 8, k = l & 255;
        wt2[l] = (k < 128) ? Wl2[k * 128 + n] : Wr2[(k - 128) * 128 + n];
    }
    int m = i - 73728;
    if (m >= 0 && m < 16384) {           // wta: [128][128]
        int n = m >> 7, k = m & 127;
        wta[m] = Wa2[k * 128 + n];
    }
}

// ---------------- aggregation ----------------
__global__ void k_agg128(const float* __restrict__ h, const int* __restrict__ rowptr,
                         const int* __restrict__ deg, const float* __restrict__ inv,
                         const int* __restrict__ csr, float* __restrict__ mean, int N) {
    int w = (blockIdx.x * blockDim.x + threadIdx.x) >> 5;
    int lane = threadIdx.x & 31;
    if (w >= N) return;
    int start = rowptr[w];
    int d = deg[w];
    float4 acc = make_float4(0.f, 0.f, 0.f, 0.f);
    int i = 0;
    for (; i + 4 <= d; i += 4) {
        int s0 = __ldg(&csr[start + i]);
        int s1 = __ldg(&csr[start + i + 1]);
        int s2 = __ldg(&csr[start + i + 2]);
        int s3 = __ldg(&csr[start + i + 3]);
        float4 v0 = __ldg((const float4*)(h + (size_t)s0 * 128) + lane);
        float4 v1 = __ldg((const float4*)(h + (size_t)s1 * 128) + lane);
        float4 v2 = __ldg((const float4*)(h + (size_t)s2 * 128) + lane);
        float4 v3 = __ldg((const float4*)(h + (size_t)s3 * 128) + lane);
        acc.x += v0.x + v1.x + v2.x + v3.x;
        acc.y += v0.y + v1.y + v2.y + v3.y;
        acc.z += v0.z + v1.z + v2.z + v3.z;
        acc.w += v0.w + v1.w + v2.w + v3.w;
    }
    for (; i < d; i++) {
        int s = __ldg(&csr[start + i]);
        float4 v = __ldg((const float4*)(h + (size_t)s * 128) + lane);
        acc.x += v.x; acc.y += v.y; acc.z += v.z; acc.w += v.w;
    }
    float iv = inv[w];
    acc.x *= iv; acc.y *= iv; acc.z *= iv; acc.w *= iv;
    ((float4*)(mean + (size_t)w * 128))[lane] = acc;
}

__global__ void k_agg32(const float* __restrict__ h, const int* __restrict__ rowptr,
                        const int* __restrict__ deg, const float* __restrict__ inv,
                        const int* __restrict__ csr, float* __restrict__ mean, int N) {
    int w = (blockIdx.x * blockDim.x + threadIdx.x) >> 5;
    int lane = threadIdx.x & 31;
    if (w >= N) return;
    int start = rowptr[w];
    int d = deg[w];
    float acc = 0.f;
    int i = 0;
    for (; i + 4 <= d; i += 4) {
        int s0 = __ldg(&csr[start + i]);
        int s1 = __ldg(&csr[start + i + 1]);
        int s2 = __ldg(&csr[start + i + 2]);
        int s3 = __ldg(&csr[start + i + 3]);
        acc += __ldg(&h[(size_t)s0 * 32 + lane]) + __ldg(&h[(size_t)s1 * 32 + lane])
             + __ldg(&h[(size_t)s2 * 32 + lane]) + __ldg(&h[(size_t)s3 * 32 + lane]);
    }
    for (; i < d; i++) {
        int s = __ldg(&csr[start + i]);
        acc += __ldg(&h[(size_t)s * 32 + lane]);
    }
    mean[(size_t)w * 32 + lane] = acc * inv[w];
}

// ---------------- bf16-split tensor-core dual GEMM ----------------
// C[M x 128] = act( A1@W1 + (A2?@W2) + bias )
// Wt: [128 n][Ktot k], Kper = K of each input. 3-product split: hh + lh + hl.
#define APAD 20   // uint32 stride (16 pairs + 4 pad) -> conflict-free frags

__global__ __launch_bounds__(256)
void k_gemm_mma(const float* __restrict__ A1, const float* __restrict__ A2,
                const float* __restrict__ Wt, const float* __restrict__ bias,
                float* __restrict__ C, int M, int Kper, int relu) {
    __shared__ uint32_t sAh[128 * APAD], sAl[128 * APAD];
    __shared__ uint32_t sBh[128 * APAD], sBl[128 * APAD];

    int tid = threadIdx.x;
    int lane = tid & 31;
    int w = tid >> 5;
    int wm = (w >> 2) * 64;       // warp row offset   (2 warps over m)
    int wn = (w & 3) * 32;        // warp col offset   (4 warps over n)
    int m0 = blockIdx.x * 128;
    int r = lane >> 2, cc = lane & 3;

    float acc[4][4][4];
#pragma unroll
    for (int a = 0; a < 4; a++)
#pragma unroll
        for (int b = 0; b < 4; b++)
#pragma unroll
            for (int q = 0; q < 4; q++) acc[a][b][q] = 0.f;

    const int nA = Kper >> 5;
    const int nch = (A2 != nullptr) ? 2 * nA : nA;
    const int Ktot = nch << 5;

    for (int ch = 0; ch < nch; ch++) {
        const float* src = (ch < nA) ? A1 : A2;
        int coff = ((ch < nA) ? ch : ch - nA) << 5;

        // fill A tile: 128 rows x 32 k
#pragma unroll
        for (int q = 0; q < 4; q++) {
            int lin = tid + (q << 8);          // 0..1023
            int m = lin >> 3;
            int k4 = (lin & 7) << 2;
            int gm = m0 + m;
            float4 v = make_float4(0.f, 0.f, 0.f, 0.f);
            if (gm < M) v = *(const float4*)&src[(size_t)gm * Kper + coff + k4];
            __nv_bfloat16 h0, l0, h1, l1, h2, l2, h3, l3;
            bf16_split(v.x, h0, l0); bf16_split(v.y, h1, l1);
            bf16_split(v.z, h2, l2); bf16_split(v.w, h3, l3);
            int base = m * APAD + (k4 >> 1);
            sAh[base]     = pack_bf(h0, h1);
            sAh[base + 1] = pack_bf(h2, h3);
            sAl[base]     = pack_bf(l0, l1);
            sAl[base + 1] = pack_bf(l2, l3);
        }
        // fill B tile: 128 n-rows x 32 k
#pragma unroll
        for (int q = 0; q < 4; q++) {
            int lin = tid + (q << 8);
            int n = lin >> 3;
            int k4 = (lin & 7) << 2;
            float4 v = *(const float4*)&Wt[(size_t)n * Ktot + (ch << 5) + k4];
            __nv_bfloat16 h0, l0, h1, l1, h2, l2, h3, l3;
            bf16_split(v.x, h0, l0); bf16_split(v.y, h1, l1);
            bf16_split(v.z, h2, l2); bf16_split(v.w, h3, l3);
            int base = n * APAD + (k4 >> 1);
            sBh[base]     = pack_bf(h0, h1);
            sBh[base + 1] = pack_bf(h2, h3);
            sBl[base]     = pack_bf(l0, l1);
            sBl[base + 1] = pack_bf(l2, l3);
        }
        __syncthreads();

#pragma unroll
        for (int ks = 0; ks < 2; ks++) {
            int kb = ks * 8;
            uint32_t ah[4][4], bh[4][2];
#pragma unroll
            for (int mt = 0; mt < 4; mt++) {
                int row = wm + mt * 16;
                ah[mt][0] = sAh[(row + r) * APAD + kb + cc];
                ah[mt][1] = sAh[(row + r + 8) * APAD + kb + cc];
                ah[mt][2] = sAh[(row + r) * APAD + kb + cc + 4];
                ah[mt][3] = sAh[(row + r + 8) * APAD + kb + cc + 4];
            }
#pragma unroll
            for (int nt = 0; nt < 4; nt++) {
                int col = wn + nt * 8;
                bh[nt][0] = sBh[(col + r) * APAD + kb + cc];
                bh[nt][1] = sBh[(col + r) * APAD + kb + cc + 4];
            }
            // hi * hi
#pragma unroll
            for (int mt = 0; mt < 4; mt++)
#pragma unroll
                for (int nt = 0; nt < 4; nt++)
                    mma_bf16(acc[mt][nt], ah[mt], bh[nt]);
            // lo * hi
            {
                uint32_t al[4][4];
#pragma unroll
                for (int mt = 0; mt < 4; mt++) {
                    int row = wm + mt * 16;
                    al[mt][0] = sAl[(row + r) * APAD + kb + cc];
                    al[mt][1] = sAl[(row + r + 8) * APAD + kb + cc];
                    al[mt][2] = sAl[(row + r) * APAD + kb + cc + 4];
                    al[mt][3] = sAl[(row + r + 8) * APAD + kb + cc + 4];
                }
#pragma unroll
                for (int mt = 0; mt < 4; mt++)
#pragma unroll
                    for (int nt = 0; nt < 4; nt++)
                        mma_bf16(acc[mt][nt], al[mt], bh[nt]);
            }
            // hi * lo
            {
                uint32_t bl[4][2];
#pragma unroll
                for (int nt = 0; nt < 4; nt++) {
                    int col = wn + nt * 8;
                    bl[nt][0] = sBl[(col + r) * APAD + kb + cc];
                    bl[nt][1] = sBl[(col + r) * APAD + kb + cc + 4];
                }
#pragma unroll
                for (int mt = 0; mt < 4; mt++)
#pragma unroll
                    for (int nt = 0; nt < 4; nt++)
                        mma_bf16(acc[mt][nt], ah[mt], bl[nt]);
            }
        }
        __syncthreads();
    }

    // epilogue
#pragma unroll
    for (int mt = 0; mt < 4; mt++) {
#pragma unroll
        for (int nt = 0; nt < 4; nt++) {
            int col = wn + nt * 8 + cc * 2;
            float b0 = __ldg(&bias[col]);
            float b1 = __ldg(&bias[col + 1]);
            int gm0 = m0 + wm + mt * 16 + r;
            int gm1 = gm0 + 8;
            float v0 = acc[mt][nt][0] + b0;
            float v1 = acc[mt][nt][1] + b1;
            float v2 = acc[mt][nt][2] + b0;
            float v3 = acc[mt][nt][3] + b1;
            if (relu) {
                v0 = fmaxf(v0, 0.f); v1 = fmaxf(v1, 0.f);
                v2 = fmaxf(v2, 0.f); v3 = fmaxf(v3, 0.f);
            }
            if (gm0 < M) *(float2*)&C[(size_t)gm0 * 128 + col] = make_float2(v0, v1);
            if (gm1 < M) *(float2*)&C[(size_t)gm1 * 128 + col] = make_float2(v2, v3);
        }
    }
}

// ---------------- heads ----------------
__global__ void k_final1(const float* __restrict__ h, const float* __restrict__ Wfc,
                         const float* __restrict__ bfc, const float* __restrict__ Wa1,
                         const float* __restrict__ ba1, float* __restrict__ d13,
                         float* __restrict__ a1, int M) {
    int gw = (blockIdx.x * blockDim.x + threadIdx.x) >> 5;
    int lane = threadIdx.x & 31;
    if (gw >= M) return;
    const float* hr = h + (size_t)gw * 128;
    float s0 = 0.f, s2 = 0.f;
    for (int k = lane; k < 128; k += 32) {
        float hv = hr[k];
        s0 += hv * __ldg(&Wfc[k * 3 + 0]);
        s2 += hv * __ldg(&Wfc[k * 3 + 2]);
    }
#pragma unroll
    for (int o = 16; o; o >>= 1) {
        s0 += __shfl_xor_sync(0xffffffffu, s0, o);
        s2 += __shfl_xor_sync(0xffffffffu, s2, o);
    }
    float d1 = s0 + __ldg(&bfc[0]);
    float d3 = s2 + __ldg(&bfc[2]);
    if (lane == 0) { d13[gw * 2] = d1; d13[gw * 2 + 1] = d3; }
    for (int j = lane; j < 128; j += 32) {
        float v = d1 * __ldg(&Wa1[j]) + d3 * __ldg(&Wa1[128 + j]) + __ldg(&ba1[j]);
        a1[(size_t)gw * 128 + j] = fmaxf(v, 0.f);
    }
}

__global__ void k_final3(const float* __restrict__ a2, const float* __restrict__ d13,
                         const float* __restrict__ Wao, const float* __restrict__ bao,
                         const int* __restrict__ batch, float* gs, int* gcnt, int M) {
    int gw = (blockIdx.x * blockDim.x + threadIdx.x) >> 5;
    int lane = threadIdx.x & 31;
    if (gw >= M) return;
    const float* ar = a2 + (size_t)gw * 128;
    float s = 0.f;
    for (int k = lane; k < 128; k += 32) s += ar[k] * __ldg(&Wao[k]);
#pragma unroll
    for (int o = 16; o; o >>= 1) s += __shfl_xor_sync(0xffffffffu, s, o);
    if (lane == 0) {
        float aux = s + __ldg(&bao[0]);
        int b = batch[gw];
        atomicAdd(&gs[b * 3 + 0], d13[gw * 2]);
        atomicAdd(&gs[b * 3 + 1], aux);
        atomicAdd(&gs[b * 3 + 2], d13[gw * 2 + 1]);
        atomicAdd(&gcnt[b], 1);
    }
}

__global__ void k_final4(const float* __restrict__ gs, const int* __restrict__ gcnt,
                         float* __restrict__ out) {
    int i = threadIdx.x;
    if (i < CG * 3) {
        int g = i / 3;
        int c = gcnt[g];
        out[i] = gs[i] / (float)(c > 0 ? c : 1);
    }
}

// ---------------- host launch ----------------
extern "C" void kernel_launch(void* const* d_in, const int* in_sizes, int n_in,
                              void* d_out, int out_size) {
    const float* x     = (const float*)d_in[0];
    const int*   ei    = (const int*)d_in[1];
    const int*   batch = (const int*)d_in[2];
    const float* Wl0 = (const float*)d_in[3];
    const float* bl0 = (const float*)d_in[4];
    const float* Wr0 = (const float*)d_in[5];
    const float* Wl1 = (const float*)d_in[6];
    const float* bl1 = (const float*)d_in[7];
    const float* Wr1 = (const float*)d_in[8];
    const float* Wl2 = (const float*)d_in[9];
    const float* bl2 = (const float*)d_in[10];
    const float* Wr2 = (const float*)d_in[11];
    const float* Wfc = (const float*)d_in[12];
    const float* bfc = (const float*)d_in[13];
    const float* Wa1 = (const float*)d_in[14];
    const float* ba1 = (const float*)d_in[15];
    const float* Wa2 = (const float*)d_in[16];
    const float* ba2 = (const float*)d_in[17];
    const float* Wao = (const float*)d_in[18];
    const float* bao = (const float*)d_in[19];
    float* out = (float*)d_out;

    const int N = in_sizes[0] / CIN;
    const int E = in_sizes[1] / 2;

    float *h0, *h1, *mean, *d13, *inv, *gs, *wt0, *wt1, *wt2, *wta;
    int *deg, *cur, *rowptr, *bsums, *csr, *gcnt;
    cudaGetSymbolAddress((void**)&h0,     g_h0);
    cudaGetSymbolAddress((void**)&h1,     g_h1);
    cudaGetSymbolAddress((void**)&mean,   g_mean);
    cudaGetSymbolAddress((void**)&d13,    g_d13);
    cudaGetSymbolAddress((void**)&inv,    g_inv);
    cudaGetSymbolAddress((void**)&deg,    g_deg);
    cudaGetSymbolAddress((void**)&cur,    g_cur);
    cudaGetSymbolAddress((void**)&rowptr, g_rowptr);
    cudaGetSymbolAddress((void**)&bsums,  g_bsums);
    cudaGetSymbolAddress((void**)&csr,    g_csr);
    cudaGetSymbolAddress((void**)&gs,     g_gs);
    cudaGetSymbolAddress((void**)&gcnt,   g_gcnt);
    cudaGetSymbolAddress((void**)&wt0,    g_wt0);
    cudaGetSymbolAddress((void**)&wt1,    g_wt1);
    cudaGetSymbolAddress((void**)&wt2,    g_wt2);
    cudaGetSymbolAddress((void**)&wta,    g_wta);

    const int nbScan = (N + 1023) / 1024;
    const int gemmBlocks = (N + 127) / 128;
    const int warpNodeBlocks = (N * 32 + 255) / 256;

    // ---- CSR build + weight prep ----
    k_zero<<<(N + 255) / 256, 256>>>(deg, cur, gs, gcnt, N);
    k_hist<<<4096, 256>>>(ei, deg, E);
    k_prep<<<352, 256>>>(Wl0, Wr0, Wl1, Wr1, Wl2, Wr2, Wa2, wt0, wt1, wt2, wta);
    k_scan1<<<nbScan, 1024>>>(deg, rowptr, bsums, N);
    k_scan2<<<1, 128>>>(bsums, nbScan);
    k_scan3<<<(N + 255) / 256, 256>>>(rowptr, bsums, deg, inv, N);
    k_fill<<<4096, 256>>>(ei, rowptr, cur, csr, E);

    // ---- layer 0 (Kper=32) ----
    k_agg32<<<warpNodeBlocks, 256>>>(x, rowptr, deg, inv, csr, mean, N);
    k_gemm_mma<<<gemmBlocks, 256>>>(mean, x, wt0, bl0, h0, N, CIN, 1);

    // ---- layer 1 (Kper=128) ----
    k_agg128<<<warpNodeBlocks, 256>>>(h0, rowptr, deg, inv, csr, mean, N);
    k_gemm_mma<<<gemmBlocks, 256>>>(mean, h0, wt1, bl1, h1, N, CH, 1);

    // ---- layer 2 (Kper=128) ----
    k_agg128<<<warpNodeBlocks, 256>>>(h1, rowptr, deg, inv, csr, mean, N);
    k_gemm_mma<<<gemmBlocks, 256>>>(mean, h1, wt2, bl2, h0, N, CH, 1);

    // ---- heads ----
    k_final1<<<warpNodeBlocks, 256>>>(h0, Wfc, bfc, Wa1, ba1, d13, mean, N);
    k_gemm_mma<<<gemmBlocks, 256>>>(mean, nullptr, wta, ba2, h1, N, CH, 1);
    k_final3<<<warpNodeBlocks, 256>>>(h1, d13, Wao, bao, batch, gs, gcnt, N);
    k_final4<<<1, 256>>>(gs, gcnt, out);
}